// round 17
// baseline (speedup 1.0000x reference)
#include <cuda_runtime.h>
#include <math.h>

#define C 128
#define CV 32            // C/4 float4 per row
#define HID 8
#define NB 16

#define NBLOCKS 592      // 4 blocks/SM x 148 SMs; co-residency guaranteed by
                         // __launch_bounds__(256,4) (regs<=64, smem 17KB/blk)

// Scratch (no allocations allowed). Zero-initialized at load; the end-ticket
// resets g_done/g_done2/g_phase and the MLP block zeroes g_sums/g_counts,
// so every call (correctness, capture, replay) starts from zeros.
__device__ float g_sums[NB][C];
__device__ float g_counts[NB];
__device__ float g_gate[NB][C];
__device__ unsigned int g_done;    // reduce-phase ticket
__device__ unsigned int g_phase;   // gate-ready flag
__device__ unsigned int g_done2;   // apply-phase ticket (cleanup)

__device__ __forceinline__ int lower_bound_idx(const int* __restrict__ bidx,
                                               int lo, int hi, int val) {
    while (lo < hi) {
        int mid = (lo + hi) >> 1;
        if (bidx[mid] < val) lo = mid + 1; else hi = mid;
    }
    return lo;
}

// ---------------------------------------------------------------------------
// Single persistent kernel: reduce -> ticket -> (last block: MLP) -> flag ->
// spin -> apply. Eliminates 2 launch gaps + mlp launch (~7us measured).
// Phase bodies are the R13 measured-best forms, unchanged.
// ---------------------------------------------------------------------------
__global__ __launch_bounds__(256, 4) void fused_kernel(
    const float4* __restrict__ x, const int* __restrict__ bidx,
    const float* __restrict__ W1, const float* __restrict__ b1,
    const float* __restrict__ W2, const float* __restrict__ b2,
    float4* __restrict__ out, int n, int rows_per_block)
{
    __shared__ float4 s_gate[NB][CV];   // 8 KB
    __shared__ float  s_mean[NB][C];    // 8 KB (used by last block only)
    __shared__ float  s_h[NB][HID];
    __shared__ unsigned int s_last;

    int tid  = threadIdx.x;
    int warp = tid >> 5;
    int lane = tid & 31;

    int row0 = blockIdx.x * rows_per_block;
    int row1 = row0 + rows_per_block;
    if (row1 > n) row1 = n;

    // ================= phase 1: segment sum (R13 body) =================
    if (row0 < row1) {
        int b_first = bidx[row0];
        int b_last  = bidx[row1 - 1];

        int seg_start = row0;
        for (int b = b_first; b <= b_last; b++) {
            int seg_end = (b == b_last) ? row1
                        : lower_bound_idx(bidx, seg_start, row1, b + 1);

            float4 accA = make_float4(0.f, 0.f, 0.f, 0.f);
            float4 accB = make_float4(0.f, 0.f, 0.f, 0.f);

            int r = seg_start + warp;
            for (; r + 56 < seg_end; r += 64) {
                float4 v0 = x[(size_t)(r)      * CV + lane];
                float4 v1 = x[(size_t)(r + 8)  * CV + lane];
                float4 v2 = x[(size_t)(r + 16) * CV + lane];
                float4 v3 = x[(size_t)(r + 24) * CV + lane];
                float4 v4 = x[(size_t)(r + 32) * CV + lane];
                float4 v5 = x[(size_t)(r + 40) * CV + lane];
                float4 v6 = x[(size_t)(r + 48) * CV + lane];
                float4 v7 = x[(size_t)(r + 56) * CV + lane];
                accA.x += v0.x; accA.y += v0.y; accA.z += v0.z; accA.w += v0.w;
                accB.x += v1.x; accB.y += v1.y; accB.z += v1.z; accB.w += v1.w;
                accA.x += v2.x; accA.y += v2.y; accA.z += v2.z; accA.w += v2.w;
                accB.x += v3.x; accB.y += v3.y; accB.z += v3.z; accB.w += v3.w;
                accA.x += v4.x; accA.y += v4.y; accA.z += v4.z; accA.w += v4.w;
                accB.x += v5.x; accB.y += v5.y; accB.z += v5.z; accB.w += v5.w;
                accA.x += v6.x; accA.y += v6.y; accA.z += v6.z; accA.w += v6.w;
                accB.x += v7.x; accB.y += v7.y; accB.z += v7.z; accB.w += v7.w;
            }
            for (; r < seg_end; r += 8) {
                float4 v = x[(size_t)r * CV + lane];
                accA.x += v.x; accA.y += v.y; accA.z += v.z; accA.w += v.w;
            }

            int seg_len = seg_end - seg_start;
            if (seg_len > 0) {
                float* dst = &g_sums[b][lane * 4];
                atomicAdd(dst + 0, accA.x + accB.x);
                atomicAdd(dst + 1, accA.y + accB.y);
                atomicAdd(dst + 2, accA.z + accB.z);
                atomicAdd(dst + 3, accA.w + accB.w);
                if (lane == 0 && warp == 0)
                    atomicAdd(&g_counts[b], (float)seg_len);
            }
            seg_start = seg_end;
        }
    }

    // ================= ticket + last-block MLP =================
    __threadfence();                    // publish this block's atomics
    __syncthreads();
    if (tid == 0) {
        unsigned int old = atomicAdd(&g_done, 1u);
        s_last = (old == (unsigned int)gridDim.x - 1u) ? 1u : 0u;
    }
    __syncthreads();

    if (s_last) {
        __threadfence();                // acquire: see all blocks' sums

        for (int i = tid; i < NB * C; i += 256) {
            int b = i / C;
            float cn = fmaxf(g_counts[b], 1.0f);
            ((float*)s_mean)[i] = ((const float*)g_sums)[i] / cn;
        }
        __syncthreads();

        // reset accumulators for the next invocation
        for (int i = tid; i < NB * C; i += 256) ((float*)g_sums)[i] = 0.0f;
        if (tid < NB) g_counts[tid] = 0.0f;

        if (tid < NB * HID) {           // 128 outputs: h[b][j]
            int b = tid / HID, j = tid % HID;
            float acc = b1[j];
            #pragma unroll 8
            for (int c = 0; c < C; c++) acc += s_mean[b][c] * W1[c * HID + j];
            s_h[b][j] = fmaxf(acc, 0.0f);
        }
        __syncthreads();

        if (tid < C) {                  // gate column c = tid
            int c = tid;
            float w2c[HID];
            #pragma unroll
            for (int j = 0; j < HID; j++) w2c[j] = W2[j * C + c];
            float bias = b2[c];
            for (int b = 0; b < NB; b++) {
                float acc = bias;
                #pragma unroll
                for (int j = 0; j < HID; j++) acc += s_h[b][j] * w2c[j];
                g_gate[b][c] = 1.0f / (1.0f + expf(-acc));
            }
        }
        __syncthreads();
        __threadfence();                // publish gate before flag
        if (tid == 0) atomicExch(&g_phase, 1u);
    }

    // ================= spin for gate (volatile load + backoff) =================
    if (tid == 0) {
        volatile unsigned int* vp = &g_phase;
        while (*vp == 0u) { __nanosleep(128); }
    }
    __syncthreads();
    __threadfence();                    // acquire: order gate reads after flag

    for (int i = tid; i < NB * CV; i += 256)
        ((float4*)s_gate)[i] = ((const float4*)g_gate)[i];
    __syncthreads();

    // ================= phase 2: apply (R13 descending body) =================
    if (row0 < row1) {
        int r = row1 - 1 - warp;
        for (; r - 24 >= row0; r -= 32) {
            int r1 = r - 8, r2 = r - 16, r3 = r - 24;
            int b0  = bidx[r];
            int b1i = bidx[r1];
            int b2i = bidx[r2];
            int b3i = bidx[r3];
            float4 v0 = x[(size_t)r  * CV + lane];
            float4 v1 = x[(size_t)r1 * CV + lane];
            float4 v2 = x[(size_t)r2 * CV + lane];
            float4 v3 = x[(size_t)r3 * CV + lane];
            float4 g0 = s_gate[b0][lane];
            float4 g1 = s_gate[b1i][lane];
            float4 g2 = s_gate[b2i][lane];
            float4 g3 = s_gate[b3i][lane];
            v0.x *= g0.x; v0.y *= g0.y; v0.z *= g0.z; v0.w *= g0.w;
            v1.x *= g1.x; v1.y *= g1.y; v1.z *= g1.z; v1.w *= g1.w;
            v2.x *= g2.x; v2.y *= g2.y; v2.z *= g2.z; v2.w *= g2.w;
            v3.x *= g3.x; v3.y *= g3.y; v3.z *= g3.z; v3.w *= g3.w;
            out[(size_t)r  * CV + lane] = v0;
            out[(size_t)r1 * CV + lane] = v1;
            out[(size_t)r2 * CV + lane] = v2;
            out[(size_t)r3 * CV + lane] = v3;
        }
        for (; r >= row0; r -= 8) {
            int b = bidx[r];
            float4 v = x[(size_t)r * CV + lane];
            float4 g = s_gate[b][lane];
            v.x *= g.x; v.y *= g.y; v.z *= g.z; v.w *= g.w;
            out[(size_t)r * CV + lane] = v;
        }
    }

    // ================= cleanup ticket (reset state for next call) ==========
    __syncthreads();
    if (tid == 0) {
        __threadfence();
        unsigned int old = atomicAdd(&g_done2, 1u);
        if (old == (unsigned int)gridDim.x - 1u) {
            g_done  = 0u;
            g_done2 = 0u;
            g_phase = 0u;
            __threadfence();
        }
    }
}

// ---------------------------------------------------------------------------
extern "C" void kernel_launch(void* const* d_in, const int* in_sizes, int n_in,
                              void* d_out, int out_size)
{
    const float* x    = (const float*)d_in[0];
    const int*   bidx = (const int*)d_in[1];
    const float* W1   = (const float*)d_in[2];
    const float* b1   = (const float*)d_in[3];
    const float* W2   = (const float*)d_in[4];
    const float* b2   = (const float*)d_in[5];
    float* out = (float*)d_out;

    int n = in_sizes[1];  // number of rows (batch_idx has N entries)
    int rows_per_block = (n + NBLOCKS - 1) / NBLOCKS;

    fused_kernel<<<NBLOCKS, 256>>>((const float4*)x, bidx,
                                   W1, b1, W2, b2,
                                   (float4*)out, n, rows_per_block);
}